// round 7
// baseline (speedup 1.0000x reference)
#include <cuda_runtime.h>
#include <cuda_bf16.h>
#include <stdint.h>
#include <math.h>

// Problem constants
#define BATCH 16
#define C_IN  256
#define W_DIM 64
#define HW    4096     // 64*64
#define HWP   1024     // pooled 32*32
#define CK    32       // f/g channels
#define CH    128      // h channels
#define OC_TOT 192

// Scratch (static device globals). f/g/h/obuf hold tf32 bit patterns.
__device__ uint32_t d_f[(size_t)BATCH * CK * HW];
__device__ uint32_t d_gbuf[(size_t)BATCH * CK * HWP];
__device__ uint32_t d_hbuf[(size_t)BATCH * CH * HWP];
__device__ uint32_t d_obuf[(size_t)BATCH * HW * CH];   // [b][q][c]

// ---------------------------------------------------------------------------
// helpers
// ---------------------------------------------------------------------------
__device__ __forceinline__ uint32_t f2tf(float x) {
    uint32_t r;
    asm("cvt.rna.tf32.f32 %0, %1;" : "=r"(r) : "f"(x));
    return r;
}
__device__ __forceinline__ uint32_t f2tf_u(uint32_t xb) {
    uint32_t r;
    asm("cvt.rna.tf32.f32 %0, %1;" : "=r"(r) : "r"(xb));
    return r;
}

__device__ __forceinline__ void mma8(float* d, const uint32_t* a, const uint32_t* b) {
    asm volatile(
        "mma.sync.aligned.m16n8k8.row.col.f32.tf32.tf32.f32 "
        "{%0,%1,%2,%3},{%4,%5,%6,%7},{%8,%9},{%0,%1,%2,%3};\n"
        : "+f"(d[0]), "+f"(d[1]), "+f"(d[2]), "+f"(d[3])
        : "r"(a[0]), "r"(a[1]), "r"(a[2]), "r"(a[3]), "r"(b[0]), "r"(b[1]));
}

__device__ __forceinline__ uint32_t s2u(const void* p) {
    return (uint32_t)__cvta_generic_to_shared(p);
}

__device__ __forceinline__ void cp16(void* dst, const void* src) {
    asm volatile("cp.async.cg.shared.global [%0], [%1], 16;\n"
                 :: "r"(s2u(dst)), "l"(src));
}
__device__ __forceinline__ void cp4(void* dst, const void* src) {
    asm volatile("cp.async.ca.shared.global [%0], [%1], 4;\n"
                 :: "r"(s2u(dst)), "l"(src));
}
__device__ __forceinline__ void cp_commit() {
    asm volatile("cp.async.commit_group;\n" ::);
}
__device__ __forceinline__ void cp_wait_all() {
    asm volatile("cp.async.wait_group 0;\n" ::);
}

// A fragment (m16 x k8 tf32), smem layout [m][k], rs words/row
__device__ __forceinline__ void ldsmA(uint32_t* r, const uint32_t* base, int rs,
                                      int m_base, int k_base, int lane) {
    const uint32_t* p = base + (size_t)(m_base + (lane & 15)) * rs + k_base + ((lane >> 4) << 2);
    uint32_t addr = s2u(p);
    asm volatile("ldmatrix.sync.aligned.m8n8.x4.shared.b16 {%0,%1,%2,%3},[%4];"
                 : "=r"(r[0]), "=r"(r[1]), "=r"(r[2]), "=r"(r[3]) : "r"(addr));
}

// B fragments for two n8 tiles (k8), smem layout [n][k]
__device__ __forceinline__ void ldsmB(uint32_t* r, const uint32_t* base, int rs,
                                      int n_base, int k_base, int lane) {
    int row = n_base + (lane & 7) + (((lane >> 4) & 1) << 3);
    int col = k_base + (((lane >> 3) & 1) << 2);
    const uint32_t* p = base + (size_t)row * rs + col;
    uint32_t addr = s2u(p);
    asm volatile("ldmatrix.sync.aligned.m8n8.x4.shared.b16 {%0,%1,%2,%3},[%4];"
                 : "=r"(r[0]), "=r"(r[1]), "=r"(r[2]), "=r"(r[3]) : "r"(addr));
}

#define RS36 36    // pitch (words), 144B = 16 mod 128 -> LDSM conflict-free
#define PS   132   // pitch for 128-wide k tiles (528B = 16 mod 128)
#define APS  260   // pitch for 256-wide k tiles (1040B = 16 mod 128)

// ---------------------------------------------------------------------------
// Kernel 1: fused projection GEMM + bias + (g/h) fused 2x2 maxpool.
// Full-A resident (tf32) + double-buffered cp.async B (raw fp32, cvt in regs).
// ---------------------------------------------------------------------------
__global__ __launch_bounds__(256)
void proj_gemm(const float* __restrict__ x,
               const float* __restrict__ wf, const float* __restrict__ bf,
               const float* __restrict__ wg, const float* __restrict__ bg,
               const float* __restrict__ wh, const float* __restrict__ bh)
{
    extern __shared__ uint32_t smp[];
    uint32_t* As = smp;                       // [64 m][APS]  full K, tf32
    uint32_t* Bs = As + 64 * APS;             // 2 x [128 n][RS36] raw fp32

    const int b  = blockIdx.z;
    const int n0 = blockIdx.x * 128;
    const int m0 = blockIdx.y * 64;
    const float* xb = x + (size_t)b * C_IN * HW;

    const int t = threadIdx.x, lane = t & 31, wid = t >> 5;
    const int wm = wid & 1, wn = wid >> 1;

    // issue async B chunk (raw fp32 bits), [n][k] transposed layout
    auto issue_chunk = [&](int k0, int buf) {
        uint32_t* bd = Bs + buf * 128 * RS36;
        #pragma unroll
        for (int ii = 0; ii < 4; ii++) {
            int i = t + ii * 256;                  // < 1024
            int n  = (i & 31) + ((i >> 5) & 3) * 32;
            int k4 = (i >> 7) * 4;
            #pragma unroll
            for (int j = 0; j < 4; j++)
                cp4(&bd[n * RS36 + k4 + j], xb + (size_t)(k0 + k4 + j) * HW + n0 + n);
        }
        cp_commit();
    };

    issue_chunk(0, 0);

    // full A: [64 m][256 k] tf32 (overlaps with B chunk 0 in flight)
    #pragma unroll
    for (int ii = 0; ii < 16; ii++) {
        int i = t + ii * 256;                      // < 4096 float4 tiles
        int m = i >> 6, k4 = (i & 63) * 4;
        int oc = m0 + m;
        const float* wr;
        if (oc < 32)       wr = wf + (size_t)oc * C_IN;
        else if (oc < 64)  wr = wg + (size_t)(oc - 32) * C_IN;
        else               wr = wh + (size_t)(oc - 64) * C_IN;
        float4 v = *reinterpret_cast<const float4*>(wr + k4);
        uint4 u = make_uint4(f2tf(v.x), f2tf(v.y), f2tf(v.z), f2tf(v.w));
        *reinterpret_cast<uint4*>(&As[m * APS + k4]) = u;
    }

    float acc[2][4][4] = {};

    for (int ic = 0; ic < 8; ic++) {
        cp_wait_all();
        __syncthreads();
        if (ic + 1 < 8) issue_chunk((ic + 1) * 32, (ic + 1) & 1);

        const uint32_t* bbuf = Bs + (ic & 1) * 128 * RS36;

        #pragma unroll
        for (int kk = 0; kk < 4; kk++) {
            uint32_t a0[4], a1[4], b01[4], b23[4];
            ldsmA(a0, As, APS, wm * 32,      ic * 32 + kk * 8, lane);
            ldsmA(a1, As, APS, wm * 32 + 16, ic * 32 + kk * 8, lane);
            ldsmB(b01, bbuf, RS36, wn * 32,      kk * 8, lane);
            ldsmB(b23, bbuf, RS36, wn * 32 + 16, kk * 8, lane);
            #pragma unroll
            for (int j = 0; j < 4; j++) { b01[j] = f2tf_u(b01[j]); b23[j] = f2tf_u(b23[j]); }
            mma8(acc[0][0], a0, b01); mma8(acc[0][1], a0, b01 + 2);
            mma8(acc[0][2], a0, b23); mma8(acc[0][3], a0, b23 + 2);
            mma8(acc[1][0], a1, b01); mma8(acc[1][1], a1, b01 + 2);
            mma8(acc[1][2], a1, b23); mma8(acc[1][3], a1, b23 + 2);
        }
    }
    __syncthreads();   // all mma reads of Bs done before psm reuse

    // epilogue: f full-res; g/h fused 2x2 maxpool via smem exchange
    float* psm = reinterpret_cast<float*>(Bs);   // [64 ocl][2 rows][32 pw]

    #pragma unroll
    for (int mt = 0; mt < 2; mt++) {
        #pragma unroll
        for (int dr = 0; dr < 2; dr++) {
            int ocl = wm * 32 + mt * 16 + dr * 8 + (lane >> 2);
            int oc = m0 + ocl;
            #pragma unroll
            for (int nt = 0; nt < 4; nt++) {
                int nloc = wn * 32 + nt * 8 + 2 * (lane & 3);
                float v0 = acc[mt][nt][dr * 2 + 0];
                float v1 = acc[mt][nt][dr * 2 + 1];
                if (oc < 32) {
                    float bias = bf[oc];
                    *reinterpret_cast<uint2*>(
                        d_f + ((size_t)b * CK + oc) * HW + n0 + nloc) =
                        make_uint2(f2tf(v0 + bias), f2tf(v1 + bias));
                } else {
                    int pr = nloc >> 6;
                    int pw = (nloc & 63) >> 1;
                    psm[ocl * 64 + pr * 32 + pw] = fmaxf(v0, v1);
                }
            }
        }
    }
    __syncthreads();

    int ph = n0 >> 7;
    for (int i = t; i < 64 * 32; i += 256) {
        int ocl = i >> 5, pw = i & 31;
        int oc = m0 + ocl;
        if (oc >= 32) {
            float v = fmaxf(psm[ocl * 64 + pw], psm[ocl * 64 + 32 + pw]);
            if (oc < 64)
                d_gbuf[((size_t)b * CK + oc - 32) * HWP + ph * 32 + pw] = f2tf(v + bg[oc - 32]);
            else
                d_hbuf[((size_t)b * CH + oc - 64) * HWP + ph * 32 + pw] = f2tf(v + bh[oc - 64]);
        }
    }
}

// ---------------------------------------------------------------------------
// Kernel 2: fused flash attention, no-max softmax, cp.async double buffering.
// ---------------------------------------------------------------------------
__global__ __launch_bounds__(256)
void attn_kernel()
{
    extern __shared__ uint32_t sm[];
    uint32_t* f_s = sm;                         // [64][RS36]
    uint32_t* g_s = f_s + 64 * RS36;            // 2 x [128 l][RS36]
    uint32_t* h_s = g_s + 2 * 128 * RS36;       // 2 x [128 c][PS]
    uint32_t* p_u = h_s + 2 * 128 * PS;         // [64 q][PS]  P (tf32)
    float* row_part = reinterpret_cast<float*>(p_u + 64 * PS);  // [4 wn][64]

    const int b  = blockIdx.y;
    const int q0 = blockIdx.x * 64;
    const int t = threadIdx.x, lane = t & 31, wid = t >> 5;
    const int wm = wid & 1, wn = wid >> 1;

    const uint32_t* fb = d_f    + (size_t)b * CK * HW;
    const uint32_t* gb = d_gbuf + (size_t)b * CK * HWP;
    const uint32_t* hb = d_hbuf + (size_t)b * CH * HWP;

    auto issue_chunk = [&](int lc, int buf) {
        uint32_t* gd = g_s + buf * 128 * RS36;
        uint32_t* hd = h_s + buf * 128 * PS;
        #pragma unroll
        for (int ii = 0; ii < 4; ii++) {
            int i = t + ii * 256;
            int l  = (i & 31) + ((i >> 5) & 3) * 32;
            int c4 = (i >> 7) * 4;
            #pragma unroll
            for (int j = 0; j < 4; j++)
                cp4(&gd[l * RS36 + c4 + j], gb + (size_t)(c4 + j) * HWP + lc + l);
        }
        #pragma unroll
        for (int ii = 0; ii < 16; ii++) {
            int i = t + ii * 256;
            int c = i >> 5, l4 = (i & 31) * 4;
            cp16(&hd[c * PS + l4], hb + (size_t)c * HWP + lc + l4);
        }
        cp_commit();
    };

    issue_chunk(0, 0);

    // f tile [64 q][32 c]
    #pragma unroll
    for (int ii = 0; ii < 2; ii++) {
        int i = t + ii * 256;
        int q = i & 63, c4 = (i >> 6) * 4;
        uint4 u;
        u.x = fb[(size_t)(c4 + 0) * HW + q0 + q];
        u.y = fb[(size_t)(c4 + 1) * HW + q0 + q];
        u.z = fb[(size_t)(c4 + 2) * HW + q0 + q];
        u.w = fb[(size_t)(c4 + 3) * HW + q0 + q];
        *reinterpret_cast<uint4*>(&f_s[q * RS36 + c4]) = u;
    }

    float acc[2][4][4] = {};
    float rsum[2][2] = {};

    for (int ic = 0; ic < 8; ic++) {
        cp_wait_all();
        __syncthreads();
        if (ic + 1 < 8) issue_chunk((ic + 1) * 128, (ic + 1) & 1);

        const uint32_t* gbuf = g_s + (ic & 1) * 128 * RS36;
        const uint32_t* hbuf = h_s + (ic & 1) * 128 * PS;

        // --- S = f * g ---
        float sacc[2][4][4] = {};
        #pragma unroll
        for (int kk = 0; kk < 4; kk++) {
            uint32_t a0[4], a1[4], b01[4], b23[4];
            ldsmA(a0, f_s, RS36, wm * 32,      kk * 8, lane);
            ldsmA(a1, f_s, RS36, wm * 32 + 16, kk * 8, lane);
            ldsmB(b01, gbuf, RS36, wn * 32,      kk * 8, lane);
            ldsmB(b23, gbuf, RS36, wn * 32 + 16, kk * 8, lane);
            mma8(sacc[0][0], a0, b01); mma8(sacc[0][1], a0, b01 + 2);
            mma8(sacc[0][2], a0, b23); mma8(sacc[0][3], a0, b23 + 2);
            mma8(sacc[1][0], a1, b01); mma8(sacc[1][1], a1, b01 + 2);
            mma8(sacc[1][2], a1, b23); mma8(sacc[1][3], a1, b23 + 2);
        }

        // --- exp on fragments, partial sums, store P (tf32) ---
        #pragma unroll
        for (int mt = 0; mt < 2; mt++) {
            int rb = wm * 32 + mt * 16 + (lane >> 2);
            #pragma unroll
            for (int nt = 0; nt < 4; nt++) {
                int cl = wn * 32 + nt * 8 + 2 * (lane & 3);
                float p0 = __expf(sacc[mt][nt][0]);
                float p1 = __expf(sacc[mt][nt][1]);
                float p2 = __expf(sacc[mt][nt][2]);
                float p3 = __expf(sacc[mt][nt][3]);
                rsum[mt][0] += p0 + p1;
                rsum[mt][1] += p2 + p3;
                *reinterpret_cast<uint2*>(&p_u[rb * PS + cl]) =
                    make_uint2(f2tf(p0), f2tf(p1));
                *reinterpret_cast<uint2*>(&p_u[(rb + 8) * PS + cl]) =
                    make_uint2(f2tf(p2), f2tf(p3));
            }
        }
        __syncthreads();

        // --- O += P * h^T ---
        #pragma unroll
        for (int kk = 0; kk < 16; kk++) {
            uint32_t a0[4], a1[4], b01[4], b23[4];
            ldsmA(a0, p_u, PS, wm * 32,      kk * 8, lane);
            ldsmA(a1, p_u, PS, wm * 32 + 16, kk * 8, lane);
            ldsmB(b01, hbuf, PS, wn * 32,      kk * 8, lane);
            ldsmB(b23, hbuf, PS, wn * 32 + 16, kk * 8, lane);
            mma8(acc[0][0], a0, b01); mma8(acc[0][1], a0, b01 + 2);
            mma8(acc[0][2], a0, b23); mma8(acc[0][3], a0, b23 + 2);
            mma8(acc[1][0], a1, b01); mma8(acc[1][1], a1, b01 + 2);
            mma8(acc[1][2], a1, b23); mma8(acc[1][3], a1, b23 + 2);
        }
    }

    // final row-sum reduction
    #pragma unroll
    for (int mt = 0; mt < 2; mt++)
        #pragma unroll
        for (int hh = 0; hh < 2; hh++) {
            float s = rsum[mt][hh];
            s += __shfl_xor_sync(0xffffffffu, s, 1);
            s += __shfl_xor_sync(0xffffffffu, s, 2);
            rsum[mt][hh] = s;
        }
    if ((lane & 3) == 0) {
        #pragma unroll
        for (int mt = 0; mt < 2; mt++)
            #pragma unroll
            for (int hh = 0; hh < 2; hh++) {
                int rb = wm * 32 + mt * 16 + hh * 8 + (lane >> 2);
                row_part[wn * 64 + rb] = rsum[mt][hh];
            }
    }
    __syncthreads();

    // epilogue: normalize, store obuf [b][q][c] as tf32
    #pragma unroll
    for (int mt = 0; mt < 2; mt++) {
        int rb = wm * 32 + mt * 16 + (lane >> 2);
        float d0 = row_part[rb]     + row_part[64 + rb]     + row_part[128 + rb]     + row_part[192 + rb];
        float d1 = row_part[rb + 8] + row_part[64 + rb + 8] + row_part[128 + rb + 8] + row_part[192 + rb + 8];
        float inv0 = 1.f / d0;
        float inv1 = 1.f / d1;
        uint32_t* o0 = d_obuf + ((size_t)b * HW + q0 + rb) * CH;
        uint32_t* o1 = d_obuf + ((size_t)b * HW + q0 + rb + 8) * CH;
        #pragma unroll
        for (int nt = 0; nt < 4; nt++) {
            int cc = wn * 32 + nt * 8 + 2 * (lane & 3);
            *reinterpret_cast<uint2*>(o0 + cc) =
                make_uint2(f2tf(acc[mt][nt][0] * inv0), f2tf(acc[mt][nt][1] * inv0));
            *reinterpret_cast<uint2*>(o1 + cc) =
                make_uint2(f2tf(acc[mt][nt][2] * inv1), f2tf(acc[mt][nt][3] * inv1));
        }
    }
}

// ---------------------------------------------------------------------------
// Kernel 3: out = gamma * (wv @ o + bv) + x
// Full-A resident (tf32) + double-buffered cp16 B (obuf already tf32 bits).
// ---------------------------------------------------------------------------
__global__ __launch_bounds__(256)
void out_gemm(const float* __restrict__ x,
              const float* __restrict__ wv, const float* __restrict__ bv,
              const float* __restrict__ gamma_p, float* __restrict__ out)
{
    extern __shared__ uint32_t smo[];
    uint32_t* As = smo;                  // [64 m][PS] full K=128, tf32
    uint32_t* Bs = As + 64 * PS;         // 2 x [128 n][RS36] tf32

    const int b  = blockIdx.z;
    const int n0 = blockIdx.x * 128;
    const int m0 = blockIdx.y * 64;
    const uint32_t* ob = d_obuf + (size_t)b * HW * CH;
    const float gamma = *gamma_p;

    const int t = threadIdx.x, lane = t & 31, wid = t >> 5;
    const int wm = wid & 1, wn = wid >> 1;

    auto issue_chunk = [&](int k0, int buf) {
        uint32_t* bd = Bs + buf * 128 * RS36;
        #pragma unroll
        for (int ii = 0; ii < 4; ii++) {
            int i = t + ii * 256;              // < 1024 cp16
            int q = i >> 3, c4 = (i & 7) * 4;
            cp16(&bd[q * RS36 + c4], ob + (size_t)(n0 + q) * CH + k0 + c4);
        }
        cp_commit();
    };

    issue_chunk(0, 0);

    // full A: wv [64 m][128 k] -> tf32
    #pragma unroll
    for (int ii = 0; ii < 8; ii++) {
        int i = t + ii * 256;                  // < 2048 float4
        int m = i >> 5, k4 = (i & 31) * 4;
        float4 v = *reinterpret_cast<const float4*>(wv + (size_t)(m0 + m) * CH + k4);
        uint4 u = make_uint4(f2tf(v.x), f2tf(v.y), f2tf(v.z), f2tf(v.w));
        *reinterpret_cast<uint4*>(&As[m * PS + k4]) = u;
    }

    float acc[2][4][4] = {};

    for (int ic = 0; ic < 4; ic++) {
        cp_wait_all();
        __syncthreads();
        if (ic + 1 < 4) issue_chunk((ic + 1) * 32, (ic + 1) & 1);

        const uint32_t* bbuf = Bs + (ic & 1) * 128 * RS36;

        #pragma unroll
        for (int kk = 0; kk < 4; kk++) {
            uint32_t a0[4], a1[4], b01[4], b23[4];
            ldsmA(a0, As, PS, wm * 32,      ic * 32 + kk * 8, lane);
            ldsmA(a1, As, PS, wm * 32 + 16, ic * 32 + kk * 8, lane);
            ldsmB(b01, bbuf, RS36, wn * 32,      kk * 8, lane);
            ldsmB(b23, bbuf, RS36, wn * 32 + 16, kk * 8, lane);
            mma8(acc[0][0], a0, b01); mma8(acc[0][1], a0, b01 + 2);
            mma8(acc[0][2], a0, b23); mma8(acc[0][3], a0, b23 + 2);
            mma8(acc[1][0], a1, b01); mma8(acc[1][1], a1, b01 + 2);
            mma8(acc[1][2], a1, b23); mma8(acc[1][3], a1, b23 + 2);
        }
    }

    #pragma unroll
    for (int mt = 0; mt < 2; mt++) {
        int r0 = m0 + wm * 32 + mt * 16 + (lane >> 2);
        #pragma unroll
        for (int dr = 0; dr < 2; dr++) {
            int oc = r0 + dr * 8;
            float bias = bv[oc];
            size_t rowoff = ((size_t)b * C_IN + oc) * HW + n0;
            #pragma unroll
            for (int nt = 0; nt < 4; nt++) {
                int cc = wn * 32 + nt * 8 + 2 * (lane & 3);
                float2 xv = *reinterpret_cast<const float2*>(x + rowoff + cc);
                float2 v;
                v.x = gamma * (acc[mt][nt][dr * 2 + 0] + bias) + xv.x;
                v.y = gamma * (acc[mt][nt][dr * 2 + 1] + bias) + xv.y;
                *reinterpret_cast<float2*>(out + rowoff + cc) = v;
            }
        }
    }
}

// ---------------------------------------------------------------------------
extern "C" void kernel_launch(void* const* d_in, const int* in_sizes, int n_in,
                              void* d_out, int out_size)
{
    const float* x  = (const float*)d_in[0];
    const float* wf = (const float*)d_in[1];
    const float* bf = (const float*)d_in[2];
    const float* wg = (const float*)d_in[3];
    const float* bg = (const float*)d_in[4];
    const float* wh = (const float*)d_in[5];
    const float* bh = (const float*)d_in[6];
    const float* wv = (const float*)d_in[7];
    const float* bv = (const float*)d_in[8];
    const float* gamma = (const float*)d_in[9];
    float* out = (float*)d_out;

    const int proj_smem = (64 * APS + 2 * 128 * RS36) * (int)sizeof(uint32_t);
    const int attn_smem =
        (64 * RS36 + 2 * 128 * RS36 + 2 * 128 * PS + 64 * PS + 256) * (int)sizeof(uint32_t);
    const int out_smem  = (64 * PS + 2 * 128 * RS36) * (int)sizeof(uint32_t);

    cudaFuncSetAttribute(proj_gemm, cudaFuncAttributeMaxDynamicSharedMemorySize, proj_smem);
    cudaFuncSetAttribute(attn_kernel, cudaFuncAttributeMaxDynamicSharedMemorySize, attn_smem);
    cudaFuncSetAttribute(out_gemm, cudaFuncAttributeMaxDynamicSharedMemorySize, out_smem);

    dim3 g1(HW / 128, OC_TOT / 64, BATCH);
    proj_gemm<<<g1, 256, proj_smem>>>(x, wf, bf, wg, bg, wh, bh);

    dim3 g3(HW / 64, BATCH);
    attn_kernel<<<g3, 256, attn_smem>>>();

    dim3 g4(HW / 128, C_IN / 64, BATCH);
    out_gemm<<<g4, 256, out_smem>>>(x, wv, bv, gamma, out);
}

// round 8
// speedup vs baseline: 1.0510x; 1.0510x over previous
#include <cuda_runtime.h>
#include <cuda_bf16.h>
#include <stdint.h>
#include <math.h>

// Problem constants
#define BATCH 16
#define C_IN  256
#define W_DIM 64
#define HW    4096     // 64*64
#define HWP   1024     // pooled 32*32
#define CK    32       // f/g channels
#define CH    128      // h channels
#define OC_TOT 192

// Scratch (static device globals). tf32 bit patterns everywhere.
__device__ uint32_t d_f[(size_t)BATCH * CK * HW];
__device__ uint32_t d_gbuf[(size_t)BATCH * CK * HWP];
__device__ uint32_t d_hbuf[(size_t)BATCH * CH * HWP];
__device__ uint32_t d_obuf[(size_t)BATCH * HW * CH];   // [b][q][c]
__device__ uint32_t d_wcat[OC_TOT * C_IN];             // [oc][256] tf32 (f,g,h weights)
__device__ uint32_t d_wvt[C_IN * CH];                  // [oc][128] tf32 (wv)

// ---------------------------------------------------------------------------
// helpers
// ---------------------------------------------------------------------------
__device__ __forceinline__ uint32_t f2tf(float x) {
    uint32_t r;
    asm("cvt.rna.tf32.f32 %0, %1;" : "=r"(r) : "f"(x));
    return r;
}
__device__ __forceinline__ uint32_t f2tf_u(uint32_t xb) {
    uint32_t r;
    asm("cvt.rna.tf32.f32 %0, %1;" : "=r"(r) : "r"(xb));
    return r;
}

__device__ __forceinline__ void mma8(float* d, const uint32_t* a, const uint32_t* b) {
    asm volatile(
        "mma.sync.aligned.m16n8k8.row.col.f32.tf32.tf32.f32 "
        "{%0,%1,%2,%3},{%4,%5,%6,%7},{%8,%9},{%0,%1,%2,%3};\n"
        : "+f"(d[0]), "+f"(d[1]), "+f"(d[2]), "+f"(d[3])
        : "r"(a[0]), "r"(a[1]), "r"(a[2]), "r"(a[3]), "r"(b[0]), "r"(b[1]));
}

__device__ __forceinline__ uint32_t s2u(const void* p) {
    return (uint32_t)__cvta_generic_to_shared(p);
}

__device__ __forceinline__ void cp16(void* dst, const void* src) {
    asm volatile("cp.async.cg.shared.global [%0], [%1], 16;\n"
                 :: "r"(s2u(dst)), "l"(src));
}
__device__ __forceinline__ void cp4(void* dst, const void* src) {
    asm volatile("cp.async.ca.shared.global [%0], [%1], 4;\n"
                 :: "r"(s2u(dst)), "l"(src));
}
__device__ __forceinline__ void cp_commit() {
    asm volatile("cp.async.commit_group;\n" ::);
}
__device__ __forceinline__ void cp_wait_all() {
    asm volatile("cp.async.wait_group 0;\n" ::);
}

// A fragment (m16 x k8 tf32), smem layout [m][k], rs words/row
__device__ __forceinline__ void ldsmA(uint32_t* r, const uint32_t* base, int rs,
                                      int m_base, int k_base, int lane) {
    const uint32_t* p = base + (size_t)(m_base + (lane & 15)) * rs + k_base + ((lane >> 4) << 2);
    uint32_t addr = s2u(p);
    asm volatile("ldmatrix.sync.aligned.m8n8.x4.shared.b16 {%0,%1,%2,%3},[%4];"
                 : "=r"(r[0]), "=r"(r[1]), "=r"(r[2]), "=r"(r[3]) : "r"(addr));
}

// B fragments for two n8 tiles (k8), smem layout [n][k]
__device__ __forceinline__ void ldsmB(uint32_t* r, const uint32_t* base, int rs,
                                      int n_base, int k_base, int lane) {
    int row = n_base + (lane & 7) + (((lane >> 4) & 1) << 3);
    int col = k_base + (((lane >> 3) & 1) << 2);
    const uint32_t* p = base + (size_t)row * rs + col;
    uint32_t addr = s2u(p);
    asm volatile("ldmatrix.sync.aligned.m8n8.x4.shared.b16 {%0,%1,%2,%3},[%4];"
                 : "=r"(r[0]), "=r"(r[1]), "=r"(r[2]), "=r"(r[3]) : "r"(addr));
}

#define RS36 36    // pitch (words), 144B = 16 mod 128 -> LDSM conflict-free
#define PS   132   // pitch for 128-wide k tiles

// ---------------------------------------------------------------------------
// Kernel 0: pre-convert weights to tf32
// ---------------------------------------------------------------------------
__global__ __launch_bounds__(256)
void prep_weights(const float* __restrict__ wf, const float* __restrict__ wg,
                  const float* __restrict__ wh, const float* __restrict__ wv)
{
    int i = blockIdx.x * 256 + threadIdx.x;
    if (i < OC_TOT * C_IN) {
        int oc = i >> 8, k = i & 255;
        float v;
        if (oc < 32)       v = wf[oc * C_IN + k];
        else if (oc < 64)  v = wg[(oc - 32) * C_IN + k];
        else               v = wh[(oc - 64) * C_IN + k];
        d_wcat[i] = f2tf(v);
    }
    int j = i - OC_TOT * C_IN;
    if (j >= 0 && j < C_IN * CH) d_wvt[j] = f2tf(wv[j]);
}

// ---------------------------------------------------------------------------
// Kernel 1: projection GEMM + bias + (g/h) fused 2x2 maxpool.
// Double-buffered streaming A (tf32, cp16) + B (fp32, cp4, cvt in regs).
// smem 55KB -> 4 CTA/SM, 1 barrier per k-chunk.
// ---------------------------------------------------------------------------
__global__ __launch_bounds__(256)
void proj_gemm(const float* __restrict__ x,
               const float* __restrict__ bf, const float* __restrict__ bg,
               const float* __restrict__ bh)
{
    extern __shared__ uint32_t smp[];
    uint32_t* As = smp;                       // 2 x [64 m][RS36]
    uint32_t* Bs = As + 2 * 64 * RS36;        // 2 x [128 n][RS36]

    const int b  = blockIdx.z;
    const int n0 = blockIdx.x * 128;
    const int m0 = blockIdx.y * 64;
    const float* xb = x + (size_t)b * C_IN * HW;

    const int t = threadIdx.x, lane = t & 31, wid = t >> 5;
    const int wm = wid & 1, wn = wid >> 1;

    auto issue_chunk = [&](int k0, int buf) {
        uint32_t* ad = As + buf * 64 * RS36;
        uint32_t* bd = Bs + buf * 128 * RS36;
        // A: [64 m][32 k] tf32, cp16
        #pragma unroll
        for (int ii = 0; ii < 2; ii++) {
            int i = t + ii * 256;                 // < 512
            int m = i >> 3, k4 = (i & 7) * 4;
            cp16(&ad[m * RS36 + k4], d_wcat + (size_t)(m0 + m) * C_IN + k0 + k4);
        }
        // B: [128 n][32 k] raw fp32 (transposed gather), cp4
        #pragma unroll
        for (int ii = 0; ii < 4; ii++) {
            int i = t + ii * 256;                 // < 1024
            int n  = (i & 31) + ((i >> 5) & 3) * 32;
            int k4 = (i >> 7) * 4;
            #pragma unroll
            for (int j = 0; j < 4; j++)
                cp4(&bd[n * RS36 + k4 + j], xb + (size_t)(k0 + k4 + j) * HW + n0 + n);
        }
        cp_commit();
    };

    issue_chunk(0, 0);

    float acc[2][4][4] = {};

    for (int ic = 0; ic < 8; ic++) {
        cp_wait_all();
        __syncthreads();
        if (ic + 1 < 8) issue_chunk((ic + 1) * 32, (ic + 1) & 1);

        const uint32_t* abuf = As + (ic & 1) * 64 * RS36;
        const uint32_t* bbuf = Bs + (ic & 1) * 128 * RS36;

        #pragma unroll
        for (int kk = 0; kk < 4; kk++) {
            uint32_t a0[4], a1[4], b01[4], b23[4];
            ldsmA(a0, abuf, RS36, wm * 32,      kk * 8, lane);
            ldsmA(a1, abuf, RS36, wm * 32 + 16, kk * 8, lane);
            ldsmB(b01, bbuf, RS36, wn * 32,      kk * 8, lane);
            ldsmB(b23, bbuf, RS36, wn * 32 + 16, kk * 8, lane);
            #pragma unroll
            for (int j = 0; j < 4; j++) { b01[j] = f2tf_u(b01[j]); b23[j] = f2tf_u(b23[j]); }
            mma8(acc[0][0], a0, b01); mma8(acc[0][1], a0, b01 + 2);
            mma8(acc[0][2], a0, b23); mma8(acc[0][3], a0, b23 + 2);
            mma8(acc[1][0], a1, b01); mma8(acc[1][1], a1, b01 + 2);
            mma8(acc[1][2], a1, b23); mma8(acc[1][3], a1, b23 + 2);
        }
    }
    __syncthreads();   // all mma reads done before smem reuse

    // epilogue: f full-res; g/h fused 2x2 maxpool via smem exchange
    float* psm = reinterpret_cast<float*>(As);   // [64 ocl][2 rows][32 pw] = 4096 floats

    #pragma unroll
    for (int mt = 0; mt < 2; mt++) {
        #pragma unroll
        for (int dr = 0; dr < 2; dr++) {
            int ocl = wm * 32 + mt * 16 + dr * 8 + (lane >> 2);
            int oc = m0 + ocl;
            #pragma unroll
            for (int nt = 0; nt < 4; nt++) {
                int nloc = wn * 32 + nt * 8 + 2 * (lane & 3);
                float v0 = acc[mt][nt][dr * 2 + 0];
                float v1 = acc[mt][nt][dr * 2 + 1];
                if (oc < 32) {
                    float bias = bf[oc];
                    *reinterpret_cast<uint2*>(
                        d_f + ((size_t)b * CK + oc) * HW + n0 + nloc) =
                        make_uint2(f2tf(v0 + bias), f2tf(v1 + bias));
                } else {
                    int pr = nloc >> 6;
                    int pw = (nloc & 63) >> 1;
                    psm[ocl * 64 + pr * 32 + pw] = fmaxf(v0, v1);
                }
            }
        }
    }
    __syncthreads();

    int ph = n0 >> 7;
    for (int i = t; i < 64 * 32; i += 256) {
        int ocl = i >> 5, pw = i & 31;
        int oc = m0 + ocl;
        if (oc >= 32) {
            float v = fmaxf(psm[ocl * 64 + pw], psm[ocl * 64 + 32 + pw]);
            if (oc < 64)
                d_gbuf[((size_t)b * CK + oc - 32) * HWP + ph * 32 + pw] = f2tf(v + bg[oc - 32]);
            else
                d_hbuf[((size_t)b * CH + oc - 64) * HWP + ph * 32 + pw] = f2tf(v + bh[oc - 64]);
        }
    }
}

// ---------------------------------------------------------------------------
// Kernel 2: fused flash attention, no-max softmax, cp.async double buffering.
// ---------------------------------------------------------------------------
__global__ __launch_bounds__(256)
void attn_kernel()
{
    extern __shared__ uint32_t sm[];
    uint32_t* f_s = sm;                         // [64][RS36]
    uint32_t* g_s = f_s + 64 * RS36;            // 2 x [128 l][RS36]
    uint32_t* h_s = g_s + 2 * 128 * RS36;       // 2 x [128 c][PS]
    uint32_t* p_u = h_s + 2 * 128 * PS;         // [64 q][PS]  P (tf32)
    float* row_part = reinterpret_cast<float*>(p_u + 64 * PS);  // [4 wn][64]

    const int b  = blockIdx.y;
    const int q0 = blockIdx.x * 64;
    const int t = threadIdx.x, lane = t & 31, wid = t >> 5;
    const int wm = wid & 1, wn = wid >> 1;

    const uint32_t* fb = d_f    + (size_t)b * CK * HW;
    const uint32_t* gb = d_gbuf + (size_t)b * CK * HWP;
    const uint32_t* hb = d_hbuf + (size_t)b * CH * HWP;

    auto issue_chunk = [&](int lc, int buf) {
        uint32_t* gd = g_s + buf * 128 * RS36;
        uint32_t* hd = h_s + buf * 128 * PS;
        #pragma unroll
        for (int ii = 0; ii < 4; ii++) {
            int i = t + ii * 256;
            int l  = (i & 31) + ((i >> 5) & 3) * 32;
            int c4 = (i >> 7) * 4;
            #pragma unroll
            for (int j = 0; j < 4; j++)
                cp4(&gd[l * RS36 + c4 + j], gb + (size_t)(c4 + j) * HWP + lc + l);
        }
        #pragma unroll
        for (int ii = 0; ii < 16; ii++) {
            int i = t + ii * 256;
            int c = i >> 5, l4 = (i & 31) * 4;
            cp16(&hd[c * PS + l4], hb + (size_t)c * HWP + lc + l4);
        }
        cp_commit();
    };

    issue_chunk(0, 0);

    // f tile [64 q][32 c]
    #pragma unroll
    for (int ii = 0; ii < 2; ii++) {
        int i = t + ii * 256;
        int q = i & 63, c4 = (i >> 6) * 4;
        uint4 u;
        u.x = fb[(size_t)(c4 + 0) * HW + q0 + q];
        u.y = fb[(size_t)(c4 + 1) * HW + q0 + q];
        u.z = fb[(size_t)(c4 + 2) * HW + q0 + q];
        u.w = fb[(size_t)(c4 + 3) * HW + q0 + q];
        *reinterpret_cast<uint4*>(&f_s[q * RS36 + c4]) = u;
    }

    float acc[2][4][4] = {};
    float rsum[2][2] = {};

    for (int ic = 0; ic < 8; ic++) {
        cp_wait_all();
        __syncthreads();
        if (ic + 1 < 8) issue_chunk((ic + 1) * 128, (ic + 1) & 1);

        const uint32_t* gbuf = g_s + (ic & 1) * 128 * RS36;
        const uint32_t* hbuf = h_s + (ic & 1) * 128 * PS;

        // --- S = f * g ---
        float sacc[2][4][4] = {};
        #pragma unroll
        for (int kk = 0; kk < 4; kk++) {
            uint32_t a0[4], a1[4], b01[4], b23[4];
            ldsmA(a0, f_s, RS36, wm * 32,      kk * 8, lane);
            ldsmA(a1, f_s, RS36, wm * 32 + 16, kk * 8, lane);
            ldsmB(b01, gbuf, RS36, wn * 32,      kk * 8, lane);
            ldsmB(b23, gbuf, RS36, wn * 32 + 16, kk * 8, lane);
            mma8(sacc[0][0], a0, b01); mma8(sacc[0][1], a0, b01 + 2);
            mma8(sacc[0][2], a0, b23); mma8(sacc[0][3], a0, b23 + 2);
            mma8(sacc[1][0], a1, b01); mma8(sacc[1][1], a1, b01 + 2);
            mma8(sacc[1][2], a1, b23); mma8(sacc[1][3], a1, b23 + 2);
        }

        // --- exp on fragments, partial sums, store P (tf32) ---
        #pragma unroll
        for (int mt = 0; mt < 2; mt++) {
            int rb = wm * 32 + mt * 16 + (lane >> 2);
            #pragma unroll
            for (int nt = 0; nt < 4; nt++) {
                int cl = wn * 32 + nt * 8 + 2 * (lane & 3);
                float p0 = __expf(sacc[mt][nt][0]);
                float p1 = __expf(sacc[mt][nt][1]);
                float p2 = __expf(sacc[mt][nt][2]);
                float p3 = __expf(sacc[mt][nt][3]);
                rsum[mt][0] += p0 + p1;
                rsum[mt][1] += p2 + p3;
                *reinterpret_cast<uint2*>(&p_u[rb * PS + cl]) =
                    make_uint2(f2tf(p0), f2tf(p1));
                *reinterpret_cast<uint2*>(&p_u[(rb + 8) * PS + cl]) =
                    make_uint2(f2tf(p2), f2tf(p3));
            }
        }
        __syncthreads();

        // --- O += P * h^T ---
        #pragma unroll
        for (int kk = 0; kk < 16; kk++) {
            uint32_t a0[4], a1[4], b01[4], b23[4];
            ldsmA(a0, p_u, PS, wm * 32,      kk * 8, lane);
            ldsmA(a1, p_u, PS, wm * 32 + 16, kk * 8, lane);
            ldsmB(b01, hbuf, PS, wn * 32,      kk * 8, lane);
            ldsmB(b23, hbuf, PS, wn * 32 + 16, kk * 8, lane);
            mma8(acc[0][0], a0, b01); mma8(acc[0][1], a0, b01 + 2);
            mma8(acc[0][2], a0, b23); mma8(acc[0][3], a0, b23 + 2);
            mma8(acc[1][0], a1, b01); mma8(acc[1][1], a1, b01 + 2);
            mma8(acc[1][2], a1, b23); mma8(acc[1][3], a1, b23 + 2);
        }
    }

    // final row-sum reduction
    #pragma unroll
    for (int mt = 0; mt < 2; mt++)
        #pragma unroll
        for (int hh = 0; hh < 2; hh++) {
            float s = rsum[mt][hh];
            s += __shfl_xor_sync(0xffffffffu, s, 1);
            s += __shfl_xor_sync(0xffffffffu, s, 2);
            rsum[mt][hh] = s;
        }
    if ((lane & 3) == 0) {
        #pragma unroll
        for (int mt = 0; mt < 2; mt++)
            #pragma unroll
            for (int hh = 0; hh < 2; hh++) {
                int rb = wm * 32 + mt * 16 + hh * 8 + (lane >> 2);
                row_part[wn * 64 + rb] = rsum[mt][hh];
            }
    }
    __syncthreads();

    // epilogue: normalize, store obuf [b][q][c] as tf32
    #pragma unroll
    for (int mt = 0; mt < 2; mt++) {
        int rb = wm * 32 + mt * 16 + (lane >> 2);
        float d0 = row_part[rb]     + row_part[64 + rb]     + row_part[128 + rb]     + row_part[192 + rb];
        float d1 = row_part[rb + 8] + row_part[64 + rb + 8] + row_part[128 + rb + 8] + row_part[192 + rb + 8];
        float inv0 = 1.f / d0;
        float inv1 = 1.f / d1;
        uint32_t* o0 = d_obuf + ((size_t)b * HW + q0 + rb) * CH;
        uint32_t* o1 = d_obuf + ((size_t)b * HW + q0 + rb + 8) * CH;
        #pragma unroll
        for (int nt = 0; nt < 4; nt++) {
            int cc = wn * 32 + nt * 8 + 2 * (lane & 3);
            *reinterpret_cast<uint2*>(o0 + cc) =
                make_uint2(f2tf(acc[mt][nt][0] * inv0), f2tf(acc[mt][nt][1] * inv0));
            *reinterpret_cast<uint2*>(o1 + cc) =
                make_uint2(f2tf(acc[mt][nt][2] * inv1), f2tf(acc[mt][nt][3] * inv1));
        }
    }
}

// ---------------------------------------------------------------------------
// Kernel 3: out = gamma * (wv @ o + bv) + x
// Resident A (tf32, pre-converted, cp16) + double-buffered cp16 B.
// ---------------------------------------------------------------------------
__global__ __launch_bounds__(256)
void out_gemm(const float* __restrict__ x,
              const float* __restrict__ bv,
              const float* __restrict__ gamma_p, float* __restrict__ out)
{
    extern __shared__ uint32_t smo[];
    uint32_t* As = smo;                  // [64 m][PS] full K=128, tf32
    uint32_t* Bs = As + 64 * PS;         // 2 x [128 n][RS36] tf32

    const int b  = blockIdx.z;
    const int n0 = blockIdx.x * 128;
    const int m0 = blockIdx.y * 64;
    const uint32_t* ob = d_obuf + (size_t)b * HW * CH;
    const float gamma = *gamma_p;

    const int t = threadIdx.x, lane = t & 31, wid = t >> 5;
    const int wm = wid & 1, wn = wid >> 1;

    auto issue_chunk = [&](int k0, int buf) {
        uint32_t* bd = Bs + buf * 128 * RS36;
        #pragma unroll
        for (int ii = 0; ii < 4; ii++) {
            int i = t + ii * 256;
            int q = i >> 3, c4 = (i & 7) * 4;
            cp16(&bd[q * RS36 + c4], ob + (size_t)(n0 + q) * CH + k0 + c4);
        }
        cp_commit();
    };

    issue_chunk(0, 0);

    // full A: d_wvt [64 m][128 k] tf32, no cvt
    #pragma unroll
    for (int ii = 0; ii < 8; ii++) {
        int i = t + ii * 256;
        int m = i >> 5, k4 = (i & 31) * 4;
        uint4 u = *reinterpret_cast<const uint4*>(d_wvt + (size_t)(m0 + m) * CH + k4);
        *reinterpret_cast<uint4*>(&As[m * PS + k4]) = u;
    }

    float acc[2][4][4] = {};

    for (int ic = 0; ic < 4; ic++) {
        cp_wait_all();
        __syncthreads();
        if (ic + 1 < 4) issue_chunk((ic + 1) * 32, (ic + 1) & 1);

        const uint32_t* bbuf = Bs + (ic & 1) * 128 * RS36;

        #pragma unroll
        for (int kk = 0; kk < 4; kk++) {
            uint32_t a0[4], a1[4], b01[4], b23[4];
            ldsmA(a0, As, PS, wm * 32,      ic * 32 + kk * 8, lane);
            ldsmA(a1, As, PS, wm * 32 + 16, ic * 32 + kk * 8, lane);
            ldsmB(b01, bbuf, RS36, wn * 32,      kk * 8, lane);
            ldsmB(b23, bbuf, RS36, wn * 32 + 16, kk * 8, lane);
            mma8(acc[0][0], a0, b01); mma8(acc[0][1], a0, b01 + 2);
            mma8(acc[0][2], a0, b23); mma8(acc[0][3], a0, b23 + 2);
            mma8(acc[1][0], a1, b01); mma8(acc[1][1], a1, b01 + 2);
            mma8(acc[1][2], a1, b23); mma8(acc[1][3], a1, b23 + 2);
        }
    }

    #pragma unroll
    for (int mt = 0; mt < 2; mt++) {
        int r0 = m0 + wm * 32 + mt * 16 + (lane >> 2);
        #pragma unroll
        for (int dr = 0; dr < 2; dr++) {
            int oc = r0 + dr * 8;
            float bias = bv[oc];
            size_t rowoff = ((size_t)b * C_IN + oc) * HW + n0;
            #pragma unroll
            for (int nt = 0; nt < 4; nt++) {
                int cc = wn * 32 + nt * 8 + 2 * (lane & 3);
                float2 xv = *reinterpret_cast<const float2*>(x + rowoff + cc);
                float2 v;
                v.x = gamma * (acc[mt][nt][dr * 2 + 0] + bias) + xv.x;
                v.y = gamma * (acc[mt][nt][dr * 2 + 1] + bias) + xv.y;
                *reinterpret_cast<float2*>(out + rowoff + cc) = v;
            }
        }
    }
}

// ---------------------------------------------------------------------------
extern "C" void kernel_launch(void* const* d_in, const int* in_sizes, int n_in,
                              void* d_out, int out_size)
{
    const float* x  = (const float*)d_in[0];
    const float* wf = (const float*)d_in[1];
    const float* bf = (const float*)d_in[2];
    const float* wg = (const float*)d_in[3];
    const float* bg = (const float*)d_in[4];
    const float* wh = (const float*)d_in[5];
    const float* bh = (const float*)d_in[6];
    const float* wv = (const float*)d_in[7];
    const float* bv = (const float*)d_in[8];
    const float* gamma = (const float*)d_in[9];
    float* out = (float*)d_out;

    const int proj_smem = (2 * 64 * RS36 + 2 * 128 * RS36) * (int)sizeof(uint32_t);
    const int attn_smem =
        (64 * RS36 + 2 * 128 * RS36 + 2 * 128 * PS + 64 * PS + 256) * (int)sizeof(uint32_t);
    const int out_smem  = (64 * PS + 2 * 128 * RS36) * (int)sizeof(uint32_t);

    cudaFuncSetAttribute(proj_gemm, cudaFuncAttributeMaxDynamicSharedMemorySize, proj_smem);
    cudaFuncSetAttribute(attn_kernel, cudaFuncAttributeMaxDynamicSharedMemorySize, attn_smem);
    cudaFuncSetAttribute(out_gemm, cudaFuncAttributeMaxDynamicSharedMemorySize, out_smem);

    // 0) pre-convert weights to tf32
    int prep_total = OC_TOT * C_IN + C_IN * CH;
    prep_weights<<<(prep_total + 255) / 256, 256>>>(wf, wg, wh, wv);

    // 1) projections + fused pool
    dim3 g1(HW / 128, OC_TOT / 64, BATCH);
    proj_gemm<<<g1, 256, proj_smem>>>(x, bf, bg, bh);

    // 2) fused attention
    dim3 g3(HW / 64, BATCH);
    attn_kernel<<<g3, 256, attn_smem>>>();

    // 3) output conv + residual
    dim3 g4(HW / 128, C_IN / 64, BATCH);
    out_gemm<<<g4, 256, out_smem>>>(x, bv, gamma, out);
}

// round 9
// speedup vs baseline: 1.1634x; 1.1070x over previous
#include <cuda_runtime.h>
#include <cuda_bf16.h>
#include <stdint.h>
#include <math.h>

// Problem constants
#define BATCH 16
#define C_IN  256
#define W_DIM 64
#define HW    4096     // 64*64
#define HWP   1024     // pooled 32*32
#define CK    32       // f/g channels
#define CH    128      // h channels
#define OC_TOT 192

// Scratch (static device globals). tf32 bit patterns everywhere.
__device__ uint32_t d_f[(size_t)BATCH * CK * HW];
__device__ uint32_t d_gbuf[(size_t)BATCH * CK * HWP];
__device__ uint32_t d_hbuf[(size_t)BATCH * CH * HWP];
__device__ uint32_t d_obuf[(size_t)BATCH * HW * CH];   // [b][q][c]
__device__ uint32_t d_wcat[OC_TOT * C_IN];             // [oc][256] tf32 (f,g,h weights)
__device__ uint32_t d_wvt[C_IN * CH];                  // [oc][128] tf32 (wv)

// ---------------------------------------------------------------------------
// helpers
// ---------------------------------------------------------------------------
__device__ __forceinline__ uint32_t f2tf(float x) {
    uint32_t r;
    asm("cvt.rna.tf32.f32 %0, %1;" : "=r"(r) : "f"(x));
    return r;
}
__device__ __forceinline__ uint32_t f2tf_u(uint32_t xb) {
    uint32_t r;
    asm("cvt.rna.tf32.f32 %0, %1;" : "=r"(r) : "r"(xb));
    return r;
}

__device__ __forceinline__ void mma8(float* d, const uint32_t* a, const uint32_t* b) {
    asm volatile(
        "mma.sync.aligned.m16n8k8.row.col.f32.tf32.tf32.f32 "
        "{%0,%1,%2,%3},{%4,%5,%6,%7},{%8,%9},{%0,%1,%2,%3};\n"
        : "+f"(d[0]), "+f"(d[1]), "+f"(d[2]), "+f"(d[3])
        : "r"(a[0]), "r"(a[1]), "r"(a[2]), "r"(a[3]), "r"(b[0]), "r"(b[1]));
}

__device__ __forceinline__ uint32_t s2u(const void* p) {
    return (uint32_t)__cvta_generic_to_shared(p);
}

__device__ __forceinline__ void cp16(void* dst, const void* src) {
    asm volatile("cp.async.cg.shared.global [%0], [%1], 16;\n"
                 :: "r"(s2u(dst)), "l"(src));
}
__device__ __forceinline__ void cp4(void* dst, const void* src) {
    asm volatile("cp.async.ca.shared.global [%0], [%1], 4;\n"
                 :: "r"(s2u(dst)), "l"(src));
}
__device__ __forceinline__ void cp_commit() {
    asm volatile("cp.async.commit_group;\n" ::);
}
__device__ __forceinline__ void cp_wait_all() {
    asm volatile("cp.async.wait_group 0;\n" ::);
}

// A fragment (m16 x k8 tf32), smem layout [m][k], rs words/row
__device__ __forceinline__ void ldsmA(uint32_t* r, const uint32_t* base, int rs,
                                      int m_base, int k_base, int lane) {
    const uint32_t* p = base + (size_t)(m_base + (lane & 15)) * rs + k_base + ((lane >> 4) << 2);
    uint32_t addr = s2u(p);
    asm volatile("ldmatrix.sync.aligned.m8n8.x4.shared.b16 {%0,%1,%2,%3},[%4];"
                 : "=r"(r[0]), "=r"(r[1]), "=r"(r[2]), "=r"(r[3]) : "r"(addr));
}

// B fragments for two n8 tiles (k8), smem layout [n][k]
__device__ __forceinline__ void ldsmB(uint32_t* r, const uint32_t* base, int rs,
                                      int n_base, int k_base, int lane) {
    int row = n_base + (lane & 7) + (((lane >> 4) & 1) << 3);
    int col = k_base + (((lane >> 3) & 1) << 2);
    const uint32_t* p = base + (size_t)row * rs + col;
    uint32_t addr = s2u(p);
    asm volatile("ldmatrix.sync.aligned.m8n8.x4.shared.b16 {%0,%1,%2,%3},[%4];"
                 : "=r"(r[0]), "=r"(r[1]), "=r"(r[2]), "=r"(r[3]) : "r"(addr));
}

#define RS36 36    // pitch (words), 144B = 16 mod 128 -> LDSM conflict-free
#define PS   132   // pitch for 128-wide k tiles
#define HP68 68    // pitch for 64-wide k tiles (272B = 16 mod 128, cp16-aligned)

// ---------------------------------------------------------------------------
// Kernel 0: pre-convert weights to tf32
// ---------------------------------------------------------------------------
__global__ __launch_bounds__(256)
void prep_weights(const float* __restrict__ wf, const float* __restrict__ wg,
                  const float* __restrict__ wh, const float* __restrict__ wv)
{
    int i = blockIdx.x * 256 + threadIdx.x;
    if (i < OC_TOT * C_IN) {
        int oc = i >> 8, k = i & 255;
        float v;
        if (oc < 32)       v = wf[oc * C_IN + k];
        else if (oc < 64)  v = wg[(oc - 32) * C_IN + k];
        else               v = wh[(oc - 64) * C_IN + k];
        d_wcat[i] = f2tf(v);
    }
    int j = i - OC_TOT * C_IN;
    if (j >= 0 && j < C_IN * CH) d_wvt[j] = f2tf(wv[j]);
}

// ---------------------------------------------------------------------------
// Kernel 1: projection GEMM + bias + (g/h) fused 2x2 maxpool.
// Double-buffered streaming A (tf32, cp16) + B (fp32, cp4, cvt in regs).
// ---------------------------------------------------------------------------
__global__ __launch_bounds__(256)
void proj_gemm(const float* __restrict__ x,
               const float* __restrict__ bf, const float* __restrict__ bg,
               const float* __restrict__ bh)
{
    extern __shared__ uint32_t smp[];
    uint32_t* As = smp;                       // 2 x [64 m][RS36]
    uint32_t* Bs = As + 2 * 64 * RS36;        // 2 x [128 n][RS36]

    const int b  = blockIdx.z;
    const int n0 = blockIdx.x * 128;
    const int m0 = blockIdx.y * 64;
    const float* xb = x + (size_t)b * C_IN * HW;

    const int t = threadIdx.x, lane = t & 31, wid = t >> 5;
    const int wm = wid & 1, wn = wid >> 1;

    auto issue_chunk = [&](int k0, int buf) {
        uint32_t* ad = As + buf * 64 * RS36;
        uint32_t* bd = Bs + buf * 128 * RS36;
        #pragma unroll
        for (int ii = 0; ii < 2; ii++) {
            int i = t + ii * 256;                 // < 512
            int m = i >> 3, k4 = (i & 7) * 4;
            cp16(&ad[m * RS36 + k4], d_wcat + (size_t)(m0 + m) * C_IN + k0 + k4);
        }
        #pragma unroll
        for (int ii = 0; ii < 4; ii++) {
            int i = t + ii * 256;                 // < 1024
            int n  = (i & 31) + ((i >> 5) & 3) * 32;
            int k4 = (i >> 7) * 4;
            #pragma unroll
            for (int j = 0; j < 4; j++)
                cp4(&bd[n * RS36 + k4 + j], xb + (size_t)(k0 + k4 + j) * HW + n0 + n);
        }
        cp_commit();
    };

    issue_chunk(0, 0);

    float acc[2][4][4] = {};

    for (int ic = 0; ic < 8; ic++) {
        cp_wait_all();
        __syncthreads();
        if (ic + 1 < 8) issue_chunk((ic + 1) * 32, (ic + 1) & 1);

        const uint32_t* abuf = As + (ic & 1) * 64 * RS36;
        const uint32_t* bbuf = Bs + (ic & 1) * 128 * RS36;

        #pragma unroll
        for (int kk = 0; kk < 4; kk++) {
            uint32_t a0[4], a1[4], b01[4], b23[4];
            ldsmA(a0, abuf, RS36, wm * 32,      kk * 8, lane);
            ldsmA(a1, abuf, RS36, wm * 32 + 16, kk * 8, lane);
            ldsmB(b01, bbuf, RS36, wn * 32,      kk * 8, lane);
            ldsmB(b23, bbuf, RS36, wn * 32 + 16, kk * 8, lane);
            #pragma unroll
            for (int j = 0; j < 4; j++) { b01[j] = f2tf_u(b01[j]); b23[j] = f2tf_u(b23[j]); }
            mma8(acc[0][0], a0, b01); mma8(acc[0][1], a0, b01 + 2);
            mma8(acc[0][2], a0, b23); mma8(acc[0][3], a0, b23 + 2);
            mma8(acc[1][0], a1, b01); mma8(acc[1][1], a1, b01 + 2);
            mma8(acc[1][2], a1, b23); mma8(acc[1][3], a1, b23 + 2);
        }
    }
    __syncthreads();

    // epilogue: f full-res; g/h fused 2x2 maxpool via smem exchange
    float* psm = reinterpret_cast<float*>(As);   // [64 ocl][2 rows][32 pw]

    #pragma unroll
    for (int mt = 0; mt < 2; mt++) {
        #pragma unroll
        for (int dr = 0; dr < 2; dr++) {
            int ocl = wm * 32 + mt * 16 + dr * 8 + (lane >> 2);
            int oc = m0 + ocl;
            #pragma unroll
            for (int nt = 0; nt < 4; nt++) {
                int nloc = wn * 32 + nt * 8 + 2 * (lane & 3);
                float v0 = acc[mt][nt][dr * 2 + 0];
                float v1 = acc[mt][nt][dr * 2 + 1];
                if (oc < 32) {
                    float bias = bf[oc];
                    *reinterpret_cast<uint2*>(
                        d_f + ((size_t)b * CK + oc) * HW + n0 + nloc) =
                        make_uint2(f2tf(v0 + bias), f2tf(v1 + bias));
                } else {
                    int pr = nloc >> 6;
                    int pw = (nloc & 63) >> 1;
                    psm[ocl * 64 + pr * 32 + pw] = fmaxf(v0, v1);
                }
            }
        }
    }
    __syncthreads();

    int ph = n0 >> 7;
    for (int i = t; i < 64 * 32; i += 256) {
        int ocl = i >> 5, pw = i & 31;
        int oc = m0 + ocl;
        if (oc >= 32) {
            float v = fmaxf(psm[ocl * 64 + pw], psm[ocl * 64 + 32 + pw]);
            if (oc < 64)
                d_gbuf[((size_t)b * CK + oc - 32) * HWP + ph * 32 + pw] = f2tf(v + bg[oc - 32]);
            else
                d_hbuf[((size_t)b * CH + oc - 64) * HWP + ph * 32 + pw] = f2tf(v + bh[oc - 64]);
        }
    }
}

// ---------------------------------------------------------------------------
// Kernel 2: fused flash attention, no-max softmax.
// l-chunks of 64 (16 chunks), f A-fragments in registers, g/h double-buffered.
// smem 104 KiB -> 2 CTAs/SM.
// ---------------------------------------------------------------------------
#define LC 64
#define NCHUNK 16

__global__ __launch_bounds__(256, 2)
void attn_kernel()
{
    extern __shared__ uint32_t sm[];
    uint32_t* g_s = sm;                         // 2 x [64 l][RS36]
    uint32_t* h_s = g_s + 2 * 64 * RS36;        // 2 x [128 c][HP68]
    uint32_t* p_u = h_s + 2 * 128 * HP68;       // [64 q][HP68]  P (tf32)
    float* row_part = reinterpret_cast<float*>(p_u + 64 * HP68);  // [4 wn][64]

    const int b  = blockIdx.y;
    const int q0 = blockIdx.x * 64;
    const int t = threadIdx.x, lane = t & 31, wid = t >> 5;
    const int wm = wid & 1, wn = wid >> 1;

    const uint32_t* fb = d_f    + (size_t)b * CK * HW;
    const uint32_t* gb = d_gbuf + (size_t)b * CK * HWP;
    const uint32_t* hb = d_hbuf + (size_t)b * CH * HWP;

    auto issue_chunk = [&](int lc, int buf) {
        uint32_t* gd = g_s + buf * 64 * RS36;
        uint32_t* hd = h_s + buf * 128 * HP68;
        // g: [64 l][32 c] transposed gather, cp4
        #pragma unroll
        for (int ii = 0; ii < 2; ii++) {
            int i = t + ii * 256;                 // < 512
            int l  = i & 63;
            int c4 = (i >> 6) * 4;
            #pragma unroll
            for (int j = 0; j < 4; j++)
                cp4(&gd[l * RS36 + c4 + j], gb + (size_t)(c4 + j) * HWP + lc + l);
        }
        // h: [128 c][64 l] native, cp16
        #pragma unroll
        for (int ii = 0; ii < 8; ii++) {
            int i = t + ii * 256;                 // < 2048
            int c = i >> 4, l4 = (i & 15) * 4;
            cp16(&hd[c * HP68 + l4], hb + (size_t)c * HWP + lc + l4);
        }
        cp_commit();
    };

    issue_chunk(0, 0);

    // f A-fragments in registers (constant across chunks).
    // fa[mt][kk][j]: row = wm*32+mt*16+(lane>>2)+8*(j&1), col = kk*8+(lane&3)+4*(j>>1)
    uint32_t fa[2][4][4];
    {
        int r0 = q0 + wm * 32 + (lane >> 2);
        int c0 = lane & 3;
        #pragma unroll
        for (int mt = 0; mt < 2; mt++)
            #pragma unroll
            for (int kk = 0; kk < 4; kk++)
                #pragma unroll
                for (int j = 0; j < 4; j++) {
                    int row = r0 + mt * 16 + 8 * (j & 1);
                    int col = kk * 8 + c0 + 4 * (j >> 1);
                    fa[mt][kk][j] = fb[(size_t)col * HW + row];
                }
    }

    float acc[2][4][4] = {};
    float rsum[2][2] = {};

    for (int ic = 0; ic < NCHUNK; ic++) {
        cp_wait_all();
        __syncthreads();   // chunk data visible; prev O-mma reads of p_u done
        if (ic + 1 < NCHUNK) issue_chunk((ic + 1) * LC, (ic + 1) & 1);

        const uint32_t* gbuf = g_s + (ic & 1) * 64 * RS36;
        const uint32_t* hbuf = h_s + (ic & 1) * 128 * HP68;

        // --- S = f * g  (n = 64 l, warp covers 16 l) ---
        float sacc[2][2][4] = {};
        #pragma unroll
        for (int kk = 0; kk < 4; kk++) {
            uint32_t bq[4];
            ldsmB(bq, gbuf, RS36, wn * 16, kk * 8, lane);
            mma8(sacc[0][0], fa[0][kk], bq); mma8(sacc[0][1], fa[0][kk], bq + 2);
            mma8(sacc[1][0], fa[1][kk], bq); mma8(sacc[1][1], fa[1][kk], bq + 2);
        }

        // --- exp on fragments, partial sums, store P (tf32) ---
        #pragma unroll
        for (int mt = 0; mt < 2; mt++) {
            int rb = wm * 32 + mt * 16 + (lane >> 2);
            #pragma unroll
            for (int nt = 0; nt < 2; nt++) {
                int cl = wn * 16 + nt * 8 + 2 * (lane & 3);
                float p0 = __expf(sacc[mt][nt][0]);
                float p1 = __expf(sacc[mt][nt][1]);
                float p2 = __expf(sacc[mt][nt][2]);
                float p3 = __expf(sacc[mt][nt][3]);
                rsum[mt][0] += p0 + p1;
                rsum[mt][1] += p2 + p3;
                *reinterpret_cast<uint2*>(&p_u[rb * HP68 + cl]) =
                    make_uint2(f2tf(p0), f2tf(p1));
                *reinterpret_cast<uint2*>(&p_u[(rb + 8) * HP68 + cl]) =
                    make_uint2(f2tf(p2), f2tf(p3));
            }
        }
        __syncthreads();

        // --- O += P * h^T  (k = 64 l, 8 k-steps) ---
        #pragma unroll
        for (int kk = 0; kk < 8; kk++) {
            uint32_t a0[4], a1[4], b01[4], b23[4];
            ldsmA(a0, p_u, HP68, wm * 32,      kk * 8, lane);
            ldsmA(a1, p_u, HP68, wm * 32 + 16, kk * 8, lane);
            ldsmB(b01, hbuf, HP68, wn * 32,      kk * 8, lane);
            ldsmB(b23, hbuf, HP68, wn * 32 + 16, kk * 8, lane);
            mma8(acc[0][0], a0, b01); mma8(acc[0][1], a0, b01 + 2);
            mma8(acc[0][2], a0, b23); mma8(acc[0][3], a0, b23 + 2);
            mma8(acc[1][0], a1, b01); mma8(acc[1][1], a1, b01 + 2);
            mma8(acc[1][2], a1, b23); mma8(acc[1][3], a1, b23 + 2);
        }
    }

    // final row-sum reduction
    #pragma unroll
    for (int mt = 0; mt < 2; mt++)
        #pragma unroll
        for (int hh = 0; hh < 2; hh++) {
            float s = rsum[mt][hh];
            s += __shfl_xor_sync(0xffffffffu, s, 1);
            s += __shfl_xor_sync(0xffffffffu, s, 2);
            rsum[mt][hh] = s;
        }
    if ((lane & 3) == 0) {
        #pragma unroll
        for (int mt = 0; mt < 2; mt++)
            #pragma unroll
            for (int hh = 0; hh < 2; hh++) {
                int rb = wm * 32 + mt * 16 + hh * 8 + (lane >> 2);
                row_part[wn * 64 + rb] = rsum[mt][hh];
            }
    }
    __syncthreads();

    // epilogue: normalize, store obuf [b][q][c] as tf32
    #pragma unroll
    for (int mt = 0; mt < 2; mt++) {
        int rb = wm * 32 + mt * 16 + (lane >> 2);
        float d0 = row_part[rb]     + row_part[64 + rb]     + row_part[128 + rb]     + row_part[192 + rb];
        float d1 = row_part[rb + 8] + row_part[64 + rb + 8] + row_part[128 + rb + 8] + row_part[192 + rb + 8];
        float inv0 = 1.f / d0;
        float inv1 = 1.f / d1;
        uint32_t* o0 = d_obuf + ((size_t)b * HW + q0 + rb) * CH;
        uint32_t* o1 = d_obuf + ((size_t)b * HW + q0 + rb + 8) * CH;
        #pragma unroll
        for (int nt = 0; nt < 4; nt++) {
            int cc = wn * 32 + nt * 8 + 2 * (lane & 3);
            *reinterpret_cast<uint2*>(o0 + cc) =
                make_uint2(f2tf(acc[mt][nt][0] * inv0), f2tf(acc[mt][nt][1] * inv0));
            *reinterpret_cast<uint2*>(o1 + cc) =
                make_uint2(f2tf(acc[mt][nt][2] * inv1), f2tf(acc[mt][nt][3] * inv1));
        }
    }
}

// ---------------------------------------------------------------------------
// Kernel 3: out = gamma * (wv @ o + bv) + x
// Resident A (tf32, pre-converted) + double-buffered cp16 B.
// ---------------------------------------------------------------------------
__global__ __launch_bounds__(256)
void out_gemm(const float* __restrict__ x,
              const float* __restrict__ bv,
              const float* __restrict__ gamma_p, float* __restrict__ out)
{
    extern __shared__ uint32_t smo[];
    uint32_t* As = smo;                  // [64 m][PS] full K=128, tf32
    uint32_t* Bs = As + 64 * PS;         // 2 x [128 n][RS36] tf32

    const int b  = blockIdx.z;
    const int n0 = blockIdx.x * 128;
    const int m0 = blockIdx.y * 64;
    const uint32_t* ob = d_obuf + (size_t)b * HW * CH;
    const float gamma = *gamma_p;

    const int t = threadIdx.x, lane = t & 31, wid = t >> 5;
    const int wm = wid & 1, wn = wid >> 1;

    auto issue_chunk = [&](int k0, int buf) {
        uint32_t* bd = Bs + buf * 128 * RS36;
        #pragma unroll
        for (int ii = 0; ii < 4; ii++) {
            int i = t + ii * 256;
            int q = i >> 3, c4 = (i & 7) * 4;
            cp16(&bd[q * RS36 + c4], ob + (size_t)(n0 + q) * CH + k0 + c4);
        }
        cp_commit();
    };

    issue_chunk(0, 0);

    #pragma unroll
    for (int ii = 0; ii < 8; ii++) {
        int i = t + ii * 256;
        int m = i >> 5, k4 = (i & 31) * 4;
        uint4 u = *reinterpret_cast<const uint4*>(d_wvt + (size_t)(m0 + m) * CH + k4);
        *reinterpret_cast<uint4*>(&As[m * PS + k4]) = u;
    }

    float acc[2][4][4] = {};

    for (int ic = 0; ic < 4; ic++) {
        cp_wait_all();
        __syncthreads();
        if (ic + 1 < 4) issue_chunk((ic + 1) * 32, (ic + 1) & 1);

        const uint32_t* bbuf = Bs + (ic & 1) * 128 * RS36;

        #pragma unroll
        for (int kk = 0; kk < 4; kk++) {
            uint32_t a0[4], a1[4], b01[4], b23[4];
            ldsmA(a0, As, PS, wm * 32,      ic * 32 + kk * 8, lane);
            ldsmA(a1, As, PS, wm * 32 + 16, ic * 32 + kk * 8, lane);
            ldsmB(b01, bbuf, RS36, wn * 32,      kk * 8, lane);
            ldsmB(b23, bbuf, RS36, wn * 32 + 16, kk * 8, lane);
            mma8(acc[0][0], a0, b01); mma8(acc[0][1], a0, b01 + 2);
            mma8(acc[0][2], a0, b23); mma8(acc[0][3], a0, b23 + 2);
            mma8(acc[1][0], a1, b01); mma8(acc[1][1], a1, b01 + 2);
            mma8(acc[1][2], a1, b23); mma8(acc[1][3], a1, b23 + 2);
        }
    }

    #pragma unroll
    for (int mt = 0; mt < 2; mt++) {
        int r0 = m0 + wm * 32 + mt * 16 + (lane >> 2);
        #pragma unroll
        for (int dr = 0; dr < 2; dr++) {
            int oc = r0 + dr * 8;
            float bias = bv[oc];
            size_t rowoff = ((size_t)b * C_IN + oc) * HW + n0;
            #pragma unroll
            for (int nt = 0; nt < 4; nt++) {
                int cc = wn * 32 + nt * 8 + 2 * (lane & 3);
                float2 xv = *reinterpret_cast<const float2*>(x + rowoff + cc);
                float2 v;
                v.x = gamma * (acc[mt][nt][dr * 2 + 0] + bias) + xv.x;
                v.y = gamma * (acc[mt][nt][dr * 2 + 1] + bias) + xv.y;
                *reinterpret_cast<float2*>(out + rowoff + cc) = v;
            }
        }
    }
}

// ---------------------------------------------------------------------------
extern "C" void kernel_launch(void* const* d_in, const int* in_sizes, int n_in,
                              void* d_out, int out_size)
{
    const float* x  = (const float*)d_in[0];
    const float* wf = (const float*)d_in[1];
    const float* bf = (const float*)d_in[2];
    const float* wg = (const float*)d_in[3];
    const float* bg = (const float*)d_in[4];
    const float* wh = (const float*)d_in[5];
    const float* bh = (const float*)d_in[6];
    const float* wv = (const float*)d_in[7];
    const float* bv = (const float*)d_in[8];
    const float* gamma = (const float*)d_in[9];
    float* out = (float*)d_out;

    const int proj_smem = (2 * 64 * RS36 + 2 * 128 * RS36) * (int)sizeof(uint32_t);
    const int attn_smem =
        (2 * 64 * RS36 + 2 * 128 * HP68 + 64 * HP68 + 256) * (int)sizeof(uint32_t);
    const int out_smem  = (64 * PS + 2 * 128 * RS36) * (int)sizeof(uint32_t);

    cudaFuncSetAttribute(proj_gemm, cudaFuncAttributeMaxDynamicSharedMemorySize, proj_smem);
    cudaFuncSetAttribute(attn_kernel, cudaFuncAttributeMaxDynamicSharedMemorySize, attn_smem);
    cudaFuncSetAttribute(out_gemm, cudaFuncAttributeMaxDynamicSharedMemorySize, out_smem);

    // 0) pre-convert weights to tf32
    int prep_total = OC_TOT * C_IN + C_IN * CH;
    prep_weights<<<(prep_total + 255) / 256, 256>>>(wf, wg, wh, wv);

    // 1) projections + fused pool
    dim3 g1(HW / 128, OC_TOT / 64, BATCH);
    proj_gemm<<<g1, 256, proj_smem>>>(x, bf, bg, bh);

    // 2) fused attention
    dim3 g3(HW / 64, BATCH);
    attn_kernel<<<g3, 256, attn_smem>>>();

    // 3) output conv + residual
    dim3 g4(HW / 128, C_IN / 64, BATCH);
    out_gemm<<<g4, 256, out_smem>>>(x, bv, gamma, out);
}

// round 11
// speedup vs baseline: 1.1731x; 1.0083x over previous
#include <cuda_runtime.h>
#include <cuda_bf16.h>
#include <stdint.h>
#include <math.h>

// Problem constants
#define BATCH 16
#define C_IN  256
#define W_DIM 64
#define HW    4096     // 64*64
#define HWP   1024     // pooled 32*32
#define CK    32       // f/g channels
#define CH    128      // h channels
#define OC_TOT 192

// Scratch (static device globals). tf32 bit patterns everywhere.
__device__ uint32_t d_f[(size_t)BATCH * CK * HW];
__device__ uint32_t d_gbuf[(size_t)BATCH * CK * HWP];
__device__ uint32_t d_hbuf[(size_t)BATCH * CH * HWP];
__device__ uint32_t d_wcat[OC_TOT * C_IN];             // [oc][256] tf32 (f,g,h weights)
__device__ uint32_t d_wvt[C_IN * CH];                  // [oc][128] tf32 (wv)

// ---------------------------------------------------------------------------
// helpers
// ---------------------------------------------------------------------------
__device__ __forceinline__ uint32_t f2tf(float x) {
    uint32_t r;
    asm("cvt.rna.tf32.f32 %0, %1;" : "=r"(r) : "f"(x));
    return r;
}
__device__ __forceinline__ uint32_t f2tf_u(uint32_t xb) {
    uint32_t r;
    asm("cvt.rna.tf32.f32 %0, %1;" : "=r"(r) : "r"(xb));
    return r;
}

__device__ __forceinline__ void mma8(float* d, const uint32_t* a, const uint32_t* b) {
    asm volatile(
        "mma.sync.aligned.m16n8k8.row.col.f32.tf32.tf32.f32 "
        "{%0,%1,%2,%3},{%4,%5,%6,%7},{%8,%9},{%0,%1,%2,%3};\n"
        : "+f"(d[0]), "+f"(d[1]), "+f"(d[2]), "+f"(d[3])
        : "r"(a[0]), "r"(a[1]), "r"(a[2]), "r"(a[3]), "r"(b[0]), "r"(b[1]));
}

__device__ __forceinline__ uint32_t s2u(const void* p) {
    return (uint32_t)__cvta_generic_to_shared(p);
}

__device__ __forceinline__ void cp16(void* dst, const void* src) {
    asm volatile("cp.async.cg.shared.global [%0], [%1], 16;\n"
                 :: "r"(s2u(dst)), "l"(src));
}
__device__ __forceinline__ void cp4(void* dst, const void* src) {
    asm volatile("cp.async.ca.shared.global [%0], [%1], 4;\n"
                 :: "r"(s2u(dst)), "l"(src));
}
__device__ __forceinline__ void cp_commit() {
    asm volatile("cp.async.commit_group;\n" ::);
}
__device__ __forceinline__ void cp_wait_all() {
    asm volatile("cp.async.wait_group 0;\n" ::);
}

// A fragment (m16 x k8 tf32), smem layout [m][k], rs words/row
__device__ __forceinline__ void ldsmA(uint32_t* r, const uint32_t* base, int rs,
                                      int m_base, int k_base, int lane) {
    const uint32_t* p = base + (size_t)(m_base + (lane & 15)) * rs + k_base + ((lane >> 4) << 2);
    uint32_t addr = s2u(p);
    asm volatile("ldmatrix.sync.aligned.m8n8.x4.shared.b16 {%0,%1,%2,%3},[%4];"
                 : "=r"(r[0]), "=r"(r[1]), "=r"(r[2]), "=r"(r[3]) : "r"(addr));
}

// B fragments for two n8 tiles (k8), smem layout [n][k]
__device__ __forceinline__ void ldsmB(uint32_t* r, const uint32_t* base, int rs,
                                      int n_base, int k_base, int lane) {
    int row = n_base + (lane & 7) + (((lane >> 4) & 1) << 3);
    int col = k_base + (((lane >> 3) & 1) << 2);
    const uint32_t* p = base + (size_t)row * rs + col;
    uint32_t addr = s2u(p);
    asm volatile("ldmatrix.sync.aligned.m8n8.x4.shared.b16 {%0,%1,%2,%3},[%4];"
                 : "=r"(r[0]), "=r"(r[1]), "=r"(r[2]), "=r"(r[3]) : "r"(addr));
}

#define RS36 36    // pitch (words), 144B = 16 mod 128 -> LDSM conflict-free
#define PS   132   // pitch for 128-wide k tiles (528B = 16 mod 128)
#define HP68 68    // pitch for 64-wide k tiles (272B = 16 mod 128, cp16-aligned)

// ---------------------------------------------------------------------------
// Kernel 0: pre-convert weights to tf32
// ---------------------------------------------------------------------------
__global__ __launch_bounds__(256)
void prep_weights(const float* __restrict__ wf, const float* __restrict__ wg,
                  const float* __restrict__ wh, const float* __restrict__ wv)
{
    int i = blockIdx.x * 256 + threadIdx.x;
    if (i < OC_TOT * C_IN) {
        int oc = i >> 8, k = i & 255;
        float v;
        if (oc < 32)       v = wf[oc * C_IN + k];
        else if (oc < 64)  v = wg[(oc - 32) * C_IN + k];
        else               v = wh[(oc - 64) * C_IN + k];
        d_wcat[i] = f2tf(v);
    }
    int j = i - OC_TOT * C_IN;
    if (j >= 0 && j < C_IN * CH) d_wvt[j] = f2tf(wv[j]);
}

// ---------------------------------------------------------------------------
// Kernel 1: projection GEMM + bias + (g/h) fused 2x2 maxpool.
// ---------------------------------------------------------------------------
__global__ __launch_bounds__(256)
void proj_gemm(const float* __restrict__ x,
               const float* __restrict__ bf, const float* __restrict__ bg,
               const float* __restrict__ bh)
{
    extern __shared__ uint32_t smp[];
    uint32_t* As = smp;                       // 2 x [64 m][RS36]
    uint32_t* Bs = As + 2 * 64 * RS36;        // 2 x [128 n][RS36]

    const int b  = blockIdx.z;
    const int n0 = blockIdx.x * 128;
    const int m0 = blockIdx.y * 64;
    const float* xb = x + (size_t)b * C_IN * HW;

    const int t = threadIdx.x, lane = t & 31, wid = t >> 5;
    const int wm = wid & 1, wn = wid >> 1;

    auto issue_chunk = [&](int k0, int buf) {
        uint32_t* ad = As + buf * 64 * RS36;
        uint32_t* bd = Bs + buf * 128 * RS36;
        #pragma unroll
        for (int ii = 0; ii < 2; ii++) {
            int i = t + ii * 256;                 // < 512
            int m = i >> 3, k4 = (i & 7) * 4;
            cp16(&ad[m * RS36 + k4], d_wcat + (size_t)(m0 + m) * C_IN + k0 + k4);
        }
        #pragma unroll
        for (int ii = 0; ii < 4; ii++) {
            int i = t + ii * 256;                 // < 1024
            int n  = (i & 31) + ((i >> 5) & 3) * 32;
            int k4 = (i >> 7) * 4;
            #pragma unroll
            for (int j = 0; j < 4; j++)
                cp4(&bd[n * RS36 + k4 + j], xb + (size_t)(k0 + k4 + j) * HW + n0 + n);
        }
        cp_commit();
    };

    issue_chunk(0, 0);

    float acc[2][4][4] = {};

    for (int ic = 0; ic < 8; ic++) {
        cp_wait_all();
        __syncthreads();
        if (ic + 1 < 8) issue_chunk((ic + 1) * 32, (ic + 1) & 1);

        const uint32_t* abuf = As + (ic & 1) * 64 * RS36;
        const uint32_t* bbuf = Bs + (ic & 1) * 128 * RS36;

        #pragma unroll
        for (int kk = 0; kk < 4; kk++) {
            uint32_t a0[4], a1[4], b01[4], b23[4];
            ldsmA(a0, abuf, RS36, wm * 32,      kk * 8, lane);
            ldsmA(a1, abuf, RS36, wm * 32 + 16, kk * 8, lane);
            ldsmB(b01, bbuf, RS36, wn * 32,      kk * 8, lane);
            ldsmB(b23, bbuf, RS36, wn * 32 + 16, kk * 8, lane);
            #pragma unroll
            for (int j = 0; j < 4; j++) { b01[j] = f2tf_u(b01[j]); b23[j] = f2tf_u(b23[j]); }
            mma8(acc[0][0], a0, b01); mma8(acc[0][1], a0, b01 + 2);
            mma8(acc[0][2], a0, b23); mma8(acc[0][3], a0, b23 + 2);
            mma8(acc[1][0], a1, b01); mma8(acc[1][1], a1, b01 + 2);
            mma8(acc[1][2], a1, b23); mma8(acc[1][3], a1, b23 + 2);
        }
    }
    __syncthreads();

    // epilogue: f full-res; g/h fused 2x2 maxpool via smem exchange
    float* psm = reinterpret_cast<float*>(As);   // [64 ocl][2 rows][32 pw]

    #pragma unroll
    for (int mt = 0; mt < 2; mt++) {
        #pragma unroll
        for (int dr = 0; dr < 2; dr++) {
            int ocl = wm * 32 + mt * 16 + dr * 8 + (lane >> 2);
            int oc = m0 + ocl;
            #pragma unroll
            for (int nt = 0; nt < 4; nt++) {
                int nloc = wn * 32 + nt * 8 + 2 * (lane & 3);
                float v0 = acc[mt][nt][dr * 2 + 0];
                float v1 = acc[mt][nt][dr * 2 + 1];
                if (oc < 32) {
                    float bias = bf[oc];
                    *reinterpret_cast<uint2*>(
                        d_f + ((size_t)b * CK + oc) * HW + n0 + nloc) =
                        make_uint2(f2tf(v0 + bias), f2tf(v1 + bias));
                } else {
                    int pr = nloc >> 6;
                    int pw = (nloc & 63) >> 1;
                    psm[ocl * 64 + pr * 32 + pw] = fmaxf(v0, v1);
                }
            }
        }
    }
    __syncthreads();

    int ph = n0 >> 7;
    for (int i = t; i < 64 * 32; i += 256) {
        int ocl = i >> 5, pw = i & 31;
        int oc = m0 + ocl;
        if (oc >= 32) {
            float v = fmaxf(psm[ocl * 64 + pw], psm[ocl * 64 + 32 + pw]);
            if (oc < 64)
                d_gbuf[((size_t)b * CK + oc - 32) * HWP + ph * 32 + pw] = f2tf(v + bg[oc - 32]);
            else
                d_hbuf[((size_t)b * CH + oc - 64) * HWP + ph * 32 + pw] = f2tf(v + bh[oc - 64]);
        }
    }
}

// ---------------------------------------------------------------------------
// Kernel 2: fused flash attention + OUTPUT CONV + residual (out_gemm fused in).
// Mainloop: l-chunks of 64, f A-fragments in registers, g/h double-buffered.
// Epilogue: O -> smem (tf32), then out[256oc, 64q] = gamma*(wv @ O^T + bv) + x,
// streaming wv in 4 double-buffered 64-oc chunks reusing the g/h smem.
// ---------------------------------------------------------------------------
#define LC 64
#define NCHUNK 16

__global__ __launch_bounds__(256, 2)
void attn_kernel(const float* __restrict__ x,
                 const float* __restrict__ bv,
                 const float* __restrict__ gamma_p,
                 float* __restrict__ out)
{
    extern __shared__ uint32_t sm[];
    uint32_t* g_s = sm;                         // 2 x [64 l][RS36]
    uint32_t* h_s = g_s + 2 * 64 * RS36;        // 2 x [128 c][HP68]
    uint32_t* p_u = h_s + 2 * 128 * HP68;       // [64 q][HP68]  P (tf32)
    float* row_part = reinterpret_cast<float*>(p_u + 64 * HP68);  // [4 wn][64]
    // epilogue overlays (reuse g/h region, 25344 words <= 26624 available):
    uint32_t* o_s  = sm;                        // [64 q][PS]  normalized O, tf32
    uint32_t* wv_s = sm + 64 * PS;              // 2 x [64 oc][PS]

    const int b  = blockIdx.y;
    const int q0 = blockIdx.x * 64;
    const int t = threadIdx.x, lane = t & 31, wid = t >> 5;
    const int wm = wid & 1, wn = wid >> 1;

    const uint32_t* fb = d_f    + (size_t)b * CK * HW;
    const uint32_t* gb = d_gbuf + (size_t)b * CK * HWP;
    const uint32_t* hb = d_hbuf + (size_t)b * CH * HWP;

    auto issue_chunk = [&](int lc, int buf) {
        uint32_t* gd = g_s + buf * 64 * RS36;
        uint32_t* hd = h_s + buf * 128 * HP68;
        #pragma unroll
        for (int ii = 0; ii < 2; ii++) {
            int i = t + ii * 256;                 // < 512
            int l  = i & 63;
            int c4 = (i >> 6) * 4;
            #pragma unroll
            for (int j = 0; j < 4; j++)
                cp4(&gd[l * RS36 + c4 + j], gb + (size_t)(c4 + j) * HWP + lc + l);
        }
        #pragma unroll
        for (int ii = 0; ii < 8; ii++) {
            int i = t + ii * 256;                 // < 2048
            int c = i >> 4, l4 = (i & 15) * 4;
            cp16(&hd[c * HP68 + l4], hb + (size_t)c * HWP + lc + l4);
        }
        cp_commit();
    };

    issue_chunk(0, 0);

    // f A-fragments in registers (constant across chunks).
    uint32_t fa[2][4][4];
    {
        int r0 = q0 + wm * 32 + (lane >> 2);
        int c0 = lane & 3;
        #pragma unroll
        for (int mt = 0; mt < 2; mt++)
            #pragma unroll
            for (int kk = 0; kk < 4; kk++)
                #pragma unroll
                for (int j = 0; j < 4; j++) {
                    int row = r0 + mt * 16 + 8 * (j & 1);
                    int col = kk * 8 + c0 + 4 * (j >> 1);
                    fa[mt][kk][j] = fb[(size_t)col * HW + row];
                }
    }

    float acc[2][4][4] = {};
    float rsum[2][2] = {};

    for (int ic = 0; ic < NCHUNK; ic++) {
        cp_wait_all();
        __syncthreads();
        if (ic + 1 < NCHUNK) issue_chunk((ic + 1) * LC, (ic + 1) & 1);

        const uint32_t* gbuf = g_s + (ic & 1) * 64 * RS36;
        const uint32_t* hbuf = h_s + (ic & 1) * 128 * HP68;

        // --- S = f * g ---
        float sacc[2][2][4] = {};
        #pragma unroll
        for (int kk = 0; kk < 4; kk++) {
            uint32_t bq[4];
            ldsmB(bq, gbuf, RS36, wn * 16, kk * 8, lane);
            mma8(sacc[0][0], fa[0][kk], bq); mma8(sacc[0][1], fa[0][kk], bq + 2);
            mma8(sacc[1][0], fa[1][kk], bq); mma8(sacc[1][1], fa[1][kk], bq + 2);
        }

        // --- exp on fragments, partial sums, store P (tf32) ---
        #pragma unroll
        for (int mt = 0; mt < 2; mt++) {
            int rb = wm * 32 + mt * 16 + (lane >> 2);
            #pragma unroll
            for (int nt = 0; nt < 2; nt++) {
                int cl = wn * 16 + nt * 8 + 2 * (lane & 3);
                float p0 = __expf(sacc[mt][nt][0]);
                float p1 = __expf(sacc[mt][nt][1]);
                float p2 = __expf(sacc[mt][nt][2]);
                float p3 = __expf(sacc[mt][nt][3]);
                rsum[mt][0] += p0 + p1;
                rsum[mt][1] += p2 + p3;
                *reinterpret_cast<uint2*>(&p_u[rb * HP68 + cl]) =
                    make_uint2(f2tf(p0), f2tf(p1));
                *reinterpret_cast<uint2*>(&p_u[(rb + 8) * HP68 + cl]) =
                    make_uint2(f2tf(p2), f2tf(p3));
            }
        }
        __syncthreads();

        // --- O += P * h^T ---
        #pragma unroll
        for (int kk = 0; kk < 8; kk++) {
            uint32_t a0[4], a1[4], b01[4], b23[4];
            ldsmA(a0, p_u, HP68, wm * 32,      kk * 8, lane);
            ldsmA(a1, p_u, HP68, wm * 32 + 16, kk * 8, lane);
            ldsmB(b01, hbuf, HP68, wn * 32,      kk * 8, lane);
            ldsmB(b23, hbuf, HP68, wn * 32 + 16, kk * 8, lane);
            mma8(acc[0][0], a0, b01); mma8(acc[0][1], a0, b01 + 2);
            mma8(acc[0][2], a0, b23); mma8(acc[0][3], a0, b23 + 2);
            mma8(acc[1][0], a1, b01); mma8(acc[1][1], a1, b01 + 2);
            mma8(acc[1][2], a1, b23); mma8(acc[1][3], a1, b23 + 2);
        }
    }

    // final row-sum reduction
    #pragma unroll
    for (int mt = 0; mt < 2; mt++)
        #pragma unroll
        for (int hh = 0; hh < 2; hh++) {
            float s = rsum[mt][hh];
            s += __shfl_xor_sync(0xffffffffu, s, 1);
            s += __shfl_xor_sync(0xffffffffu, s, 2);
            rsum[mt][hh] = s;
        }
    if ((lane & 3) == 0) {
        #pragma unroll
        for (int mt = 0; mt < 2; mt++)
            #pragma unroll
            for (int hh = 0; hh < 2; hh++) {
                int rb = wm * 32 + mt * 16 + hh * 8 + (lane >> 2);
                row_part[wn * 64 + rb] = rsum[mt][hh];
            }
    }
    __syncthreads();   // row_part visible; all smem (g/h/p) reads done -> safe to overlay

    // --- normalize O into o_s[q][c] (tf32), issue first wv chunk ---
    auto issue_wv = [&](int mc, int buf) {
        uint32_t* ad = wv_s + buf * 64 * PS;
        #pragma unroll
        for (int ii = 0; ii < 8; ii++) {
            int i = t + ii * 256;               // < 2048
            int m = i >> 5, k4 = (i & 31) * 4;
            cp16(&ad[m * PS + k4], d_wvt + (size_t)(mc * 64 + m) * CH + k4);
        }
        cp_commit();
    };

    issue_wv(0, 0);

    #pragma unroll
    for (int mt = 0; mt < 2; mt++) {
        int rb = wm * 32 + mt * 16 + (lane >> 2);
        float d0 = row_part[rb]     + row_part[64 + rb]     + row_part[128 + rb]     + row_part[192 + rb];
        float d1 = row_part[rb + 8] + row_part[64 + rb + 8] + row_part[128 + rb + 8] + row_part[192 + rb + 8];
        float inv0 = 1.f / d0;
        float inv1 = 1.f / d1;
        #pragma unroll
        for (int nt = 0; nt < 4; nt++) {
            int cc = wn * 32 + nt * 8 + 2 * (lane & 3);
            *reinterpret_cast<uint2*>(&o_s[rb * PS + cc]) =
                make_uint2(f2tf(acc[mt][nt][0] * inv0), f2tf(acc[mt][nt][1] * inv0));
            *reinterpret_cast<uint2*>(&o_s[(rb + 8) * PS + cc]) =
                make_uint2(f2tf(acc[mt][nt][2] * inv1), f2tf(acc[mt][nt][3] * inv1));
        }
    }

    // --- out[oc, q] = gamma * (wv @ O^T + bv) + x, 4 oc-chunks of 64 ---
    const float gamma = *gamma_p;

    for (int mc = 0; mc < 4; mc++) {
        cp_wait_all();
        __syncthreads();   // wv chunk + (mc==0) o_s visible; prev A reads done
        if (mc + 1 < 4) issue_wv(mc + 1, (mc + 1) & 1);

        const uint32_t* abuf = wv_s + (mc & 1) * 64 * PS;

        float oa[2][2][4] = {};
        #pragma unroll
        for (int kk = 0; kk < 16; kk++) {
            uint32_t a0[4], a1[4], bq[4];
            ldsmA(a0, abuf, PS, wm * 32,      kk * 8, lane);
            ldsmA(a1, abuf, PS, wm * 32 + 16, kk * 8, lane);
            ldsmB(bq, o_s, PS, wn * 16, kk * 8, lane);
            mma8(oa[0][0], a0, bq); mma8(oa[0][1], a0, bq + 2);
            mma8(oa[1][0], a1, bq); mma8(oa[1][1], a1, bq + 2);
        }

        #pragma unroll
        for (int mt = 0; mt < 2; mt++) {
            #pragma unroll
            for (int dr = 0; dr < 2; dr++) {
                int oc = mc * 64 + wm * 32 + mt * 16 + dr * 8 + (lane >> 2);
                float bias = bv[oc];
                size_t rowoff = ((size_t)b * C_IN + oc) * HW + q0;
                #pragma unroll
                for (int nt = 0; nt < 2; nt++) {
                    int ql = wn * 16 + nt * 8 + 2 * (lane & 3);
                    float2 xv = *reinterpret_cast<const float2*>(x + rowoff + ql);
                    float2 v;
                    v.x = gamma * (oa[mt][nt][dr * 2 + 0] + bias) + xv.x;
                    v.y = gamma * (oa[mt][nt][dr * 2 + 1] + bias) + xv.y;
                    *reinterpret_cast<float2*>(out + rowoff + ql) = v;
                }
            }
        }
    }
}

// ---------------------------------------------------------------------------
extern "C" void kernel_launch(void* const* d_in, const int* in_sizes, int n_in,
                              void* d_out, int out_size)
{
    const float* x  = (const float*)d_in[0];
    const float* wf = (const float*)d_in[1];
    const float* bf = (const float*)d_in[2];
    const float* wg = (const float*)d_in[3];
    const float* bg = (const float*)d_in[4];
    const float* wh = (const float*)d_in[5];
    const float* bh = (const float*)d_in[6];
    const float* wv = (const float*)d_in[7];
    const float* bv = (const float*)d_in[8];
    const float* gamma = (const float*)d_in[9];
    float* out = (float*)d_out;

    const int proj_smem = (2 * 64 * RS36 + 2 * 128 * RS36) * (int)sizeof(uint32_t);
    const int attn_smem =
        (2 * 64 * RS36 + 2 * 128 * HP68 + 64 * HP68 + 256) * (int)sizeof(uint32_t);

    cudaFuncSetAttribute(proj_gemm, cudaFuncAttributeMaxDynamicSharedMemorySize, proj_smem);
    cudaFuncSetAttribute(attn_kernel, cudaFuncAttributeMaxDynamicSharedMemorySize, attn_smem);

    // 0) pre-convert weights to tf32
    int prep_total = OC_TOT * C_IN + C_IN * CH;
    prep_weights<<<(prep_total + 255) / 256, 256>>>(wf, wg, wh, wv);

    // 1) projections + fused pool
    dim3 g1(HW / 128, OC_TOT / 64, BATCH);
    proj_gemm<<<g1, 256, proj_smem>>>(x, bf, bg, bh);

    // 2) fused attention + output conv + residual
    dim3 g3(HW / 64, BATCH);
    attn_kernel<<<g3, 256, attn_smem>>>(x, bv, gamma, out);
}